// round 10
// baseline (speedup 1.0000x reference)
#include <cuda_runtime.h>
#include <math.h>
#include <float.h>

// Problem constants
#define NB 1024
#define LL 200
#define DD 128
#define KK 3
#define NEG_PAD (-65535.0f)

__device__ float g_B[KK * LL];          // working routing logits
__device__ float g_delta[3][KK * LL];   // per-iteration delta accumulators
__device__ float g_ST[DD * DD];         // S transposed: ST[e*128 + d] = S[d*128 + e]

// ---------------------------------------------------------------------------
// init: copy B_matrix into working buffer, zero deltas, build S^T
// ---------------------------------------------------------------------------
__global__ void routing_init_kernel(const float* __restrict__ Bin,
                                    const float* __restrict__ S)
{
    int idx = blockIdx.x * 256 + threadIdx.x;   // 0..16383
    int d = idx >> 7;
    int e = idx & 127;
    g_ST[e * DD + d] = S[idx];                  // coalesced read of S
    if (blockIdx.x == 0) {
        for (int t = threadIdx.x; t < KK * LL; t += 256) {
            g_B[t] = Bin[t];
            g_delta[0][t] = 0.f;
            g_delta[1][t] = 0.f;
            g_delta[2][t] = 0.f;
        }
    }
}

// ---------------------------------------------------------------------------
// update: B += delta[it]
// ---------------------------------------------------------------------------
__global__ void routing_update_kernel(int it)
{
    int t = threadIdx.x;
    if (t < KK * LL) g_B[t] += g_delta[it][t];
}

// ---------------------------------------------------------------------------
// One routing iteration, fused per batch element. NO cap staging:
// cap is streamed twice from global (coalesced LDG.128; 2nd sweep is L2-hot).
// smem ~21.6KB -> 4 CTAs/SM (32 warps, 2x occupancy vs staged version).
// ---------------------------------------------------------------------------
__global__ void __launch_bounds__(256, 4)
routing_iter_kernel(const float* __restrict__ cap,
                    const float* __restrict__ S,
                    const void*  __restrict__ seqp,
                    int it,
                    float* __restrict__ out)
{
    __shared__ float W4[LL * 4];        // softmax weights, [l][4] (k=0..2 + pad)
    __shared__ float red[8 * 384];      // cross-warp reduce scratch (12KB)
    __shared__ float u4[DD * 4];        // u packed [d][4]
    __shared__ float h4[DD * 4];        // high packed [e][4]
    __shared__ float g4[DD * 4];        // g packed [d][4]

    const int b    = blockIdx.x;
    const int tid  = threadIdx.x;
    const int warp = tid >> 5;
    const int lane = tid & 31;

    // ---- sequence length: robust to int32 vs int64 storage ---------------
    int n;
    {
        const int* si = (const int*)seqp;
        if (si[1] == 0) n = (int)(((const long long*)seqp)[b]);   // int64 layout
        else            n = si[b];                                 // int32 layout
    }

    // ---- masked softmax over L for each of the 3 routing rows (warps 0-2)
    if (warp < 3) {
        const int k = warp;
        float v[7];
        float mx = -FLT_MAX;
        #pragma unroll
        for (int i = 0; i < 7; i++) {
            int l = lane + 32 * i;
            float x = -FLT_MAX;
            if (l < LL) x = (l < n) ? g_B[k * LL + l] : NEG_PAD;
            v[i] = x;
            mx = fmaxf(mx, x);
        }
        #pragma unroll
        for (int off = 16; off; off >>= 1)
            mx = fmaxf(mx, __shfl_xor_sync(0xffffffffu, mx, off));
        float s = 0.f;
        #pragma unroll
        for (int i = 0; i < 7; i++) {
            int l = lane + 32 * i;
            float e = (l < LL) ? expf(v[i] - mx) : 0.f;
            v[i] = e;
            s += e;
        }
        #pragma unroll
        for (int off = 16; off; off >>= 1)
            s += __shfl_xor_sync(0xffffffffu, s, off);
        float inv = 1.f / s;
        #pragma unroll
        for (int i = 0; i < 7; i++) {
            int l = lane + 32 * i;
            if (l < LL) W4[l * 4 + k] = v[i] * inv;
        }
        // zero the pad channel so uninitialized smem never feeds a NaN path
        #pragma unroll
        for (int i = 0; i < 7; i++) {
            int l = lane + 32 * i;
            if (l < LL) W4[l * 4 + 3] = 0.f;
        }
    }
    __syncthreads();

    const float4* capb = (const float4*)(cap + (size_t)b * (LL * DD));

    // ---- u[k,d] = sum_l W[k,l]*cap[l,d] : warp-per-l, coalesced LDG.128 ---
    {
        float ua0x = 0.f, ua0y = 0.f, ua0z = 0.f, ua0w = 0.f;
        float ua1x = 0.f, ua1y = 0.f, ua1z = 0.f, ua1w = 0.f;
        float ua2x = 0.f, ua2y = 0.f, ua2z = 0.f, ua2w = 0.f;
        #pragma unroll 5
        for (int r = 0; r < 25; r++) {
            int l = r * 8 + warp;                       // 8 warps * 25 = 200
            float4 c  = capb[l * 32 + lane];            // coalesced 512B/warp
            float4 wv = *(const float4*)(W4 + l * 4);   // broadcast
            ua0x = fmaf(wv.x, c.x, ua0x); ua0y = fmaf(wv.x, c.y, ua0y);
            ua0z = fmaf(wv.x, c.z, ua0z); ua0w = fmaf(wv.x, c.w, ua0w);
            ua1x = fmaf(wv.y, c.x, ua1x); ua1y = fmaf(wv.y, c.y, ua1y);
            ua1z = fmaf(wv.y, c.z, ua1z); ua1w = fmaf(wv.y, c.w, ua1w);
            ua2x = fmaf(wv.z, c.x, ua2x); ua2y = fmaf(wv.z, c.y, ua2y);
            ua2z = fmaf(wv.z, c.z, ua2z); ua2w = fmaf(wv.z, c.w, ua2w);
        }
        float* rp = red + warp * 384 + lane * 4;
        *(float4*)(rp)       = make_float4(ua0x, ua0y, ua0z, ua0w);
        *(float4*)(rp + 128) = make_float4(ua1x, ua1y, ua1z, ua1w);
        *(float4*)(rp + 256) = make_float4(ua2x, ua2y, ua2z, ua2w);
    }
    __syncthreads();
    for (int t = tid; t < 384; t += 256) {              // cross-warp reduce
        float s = 0.f;
        #pragma unroll
        for (int w = 0; w < 8; w++) s += red[w * 384 + t];
        int k = t >> 7;
        int d = t & 127;
        u4[d * 4 + k] = s;
    }
    __syncthreads();

    // ---- hraw[k,e] = sum_d u[k,d]*S[d,e] : (e, d-half) split -------------
    {
        const int e = tid & 127;
        const int half = tid >> 7;
        float h0 = 0.f, h1 = 0.f, h2 = 0.f;
        const int d0 = half * 64;
        const float* Sp = S + e;
        #pragma unroll 8
        for (int d = d0; d < d0 + 64; d++) {
            float4 u = *(const float4*)(u4 + d * 4);   // broadcast
            float  s = Sp[d * DD];                     // coalesced, L1/L2-hot
            h0 = fmaf(u.x, s, h0);
            h1 = fmaf(u.y, s, h1);
            h2 = fmaf(u.z, s, h2);
        }
        red[half * 384 +       e] = h0;
        red[half * 384 + 128 + e] = h1;
        red[half * 384 + 256 + e] = h2;
    }
    __syncthreads();

    // ---- squash over k, write output, publish high -----------------------
    if (tid < 128) {
        const int e = tid;
        float h0 = red[e]       + red[384 + e];
        float h1 = red[128 + e] + red[512 + e];
        float h2 = red[256 + e] + red[640 + e];
        float sq = h0 * h0 + h1 * h1 + h2 * h2;
        float scale = (sq / (1.f + sq)) * rsqrtf(sq + 1e-9f);
        h0 *= scale; h1 *= scale; h2 *= scale;
        float* op = out + (size_t)b * (KK * DD) + e;
        op[0]      = h0;
        op[DD]     = h1;
        op[2 * DD] = h2;
        h4[e * 4 + 0] = h0;
        h4[e * 4 + 1] = h1;
        h4[e * 4 + 2] = h2;
    }
    __syncthreads();

    // ---- g[k,d] = sum_e high[k,e]*ST[e,d] : (d, e-half) split ------------
    {
        const int d = tid & 127;
        const int half = tid >> 7;
        float q0 = 0.f, q1 = 0.f, q2 = 0.f;
        const int e0 = half * 64;
        const float* STp = g_ST + d;
        #pragma unroll 8
        for (int e = e0; e < e0 + 64; e++) {
            float4 h = *(const float4*)(h4 + e * 4);   // broadcast
            float  s = STp[e * DD];                    // coalesced, L1/L2-hot
            q0 = fmaf(h.x, s, q0);
            q1 = fmaf(h.y, s, q1);
            q2 = fmaf(h.z, s, q2);
        }
        red[half * 384 +       d] = q0;
        red[half * 384 + 128 + d] = q1;
        red[half * 384 + 256 + d] = q2;
    }
    __syncthreads();
    for (int t = tid; t < 384; t += 256) {
        float gv = red[t] + red[384 + t];
        int k = t >> 7;
        int d = t & 127;
        g4[d * 4 + k] = gv;
    }
    __syncthreads();

    // ---- delta[k,l] += sum_d g[k,d]*cap[l,d] : warp-per-l, 2nd sweep -----
    {
        // preload g for this lane's 4 d's into registers (one-time)
        float g0[4], g1[4], g2[4];
        #pragma unroll
        for (int j = 0; j < 4; j++) {
            float4 gv = *(const float4*)(g4 + (lane * 4 + j) * 4);
            g0[j] = gv.x; g1[j] = gv.y; g2[j] = gv.z;
        }
        float* dp = g_delta[it];
        #pragma unroll 5
        for (int r = 0; r < 25; r++) {
            int l = r * 8 + warp;
            float4 c = capb[l * 32 + lane];            // L2-hot re-read
            float a0 = fmaf(g0[0], c.x, fmaf(g0[1], c.y, fmaf(g0[2], c.z, g0[3] * c.w)));
            float a1 = fmaf(g1[0], c.x, fmaf(g1[1], c.y, fmaf(g1[2], c.z, g1[3] * c.w)));
            float a2 = fmaf(g2[0], c.x, fmaf(g2[1], c.y, fmaf(g2[2], c.z, g2[3] * c.w)));
            #pragma unroll
            for (int off = 16; off; off >>= 1) {
                a0 += __shfl_xor_sync(0xffffffffu, a0, off);
                a1 += __shfl_xor_sync(0xffffffffu, a1, off);
                a2 += __shfl_xor_sync(0xffffffffu, a2, off);
            }
            if (lane == 0) {
                atomicAdd(dp + l,          a0);
                atomicAdd(dp + LL + l,     a1);
                atomicAdd(dp + 2 * LL + l, a2);
            }
        }
    }
}

// ---------------------------------------------------------------------------
// kernel_launch
//   d_in[0] low_capsule  f32 [1024*200*128]
//   d_in[1] B_matrix     f32 [1*3*200]
//   d_in[2] S_matrix     f32 [128*128]
//   d_in[3] seq_len      int [1024] (int32 or int64 — detected at runtime)
//   d_out  high          f32 [1024*3*128]
// ---------------------------------------------------------------------------
extern "C" void kernel_launch(void* const* d_in, const int* in_sizes, int n_in,
                              void* d_out, int out_size)
{
    (void)in_sizes; (void)n_in; (void)out_size;
    const float* cap  = (const float*)d_in[0];
    const float* Bin  = (const float*)d_in[1];
    const float* S    = (const float*)d_in[2];
    const void*  seqp = d_in[3];
    float* out = (float*)d_out;

    routing_init_kernel<<<64, 256>>>(Bin, S);

    routing_iter_kernel<<<NB, 256>>>(cap, S, seqp, 0, out);
    routing_update_kernel<<<1, 600>>>(0);
    routing_iter_kernel<<<NB, 256>>>(cap, S, seqp, 1, out);
    routing_update_kernel<<<1, 600>>>(1);
    routing_iter_kernel<<<NB, 256>>>(cap, S, seqp, 2, out);
}

// round 11
// speedup vs baseline: 1.0397x; 1.0397x over previous
#include <cuda_runtime.h>
#include <math.h>
#include <float.h>

#define NB 1024
#define LL 200
#define DD 128
#define KK 3
#define NEG_PAD (-65535.0f)
#define LSTAGE 100            // rows staged in smem; rest re-read from L2
#define ROWQ 33               // float4 per staged row (32 + 1 pad, odd -> conflict-free)

// Shared memory layout (floats):
//  cap4s [0,13200)  staged rows [100][33] float4
//  W4    [13200,14000)
//  red   [14000,17072)  [8][384] partial-sum scratch
//  u4    [17072,17584)  [d][4]
//  h4    [17584,18096)  [e][4]
//  g4    [18096,18608)  [d][4]
#define SM_FLOATS 18608
#define SMEM_BYTES (SM_FLOATS * 4)

__device__ float g_B[KK * LL];
__device__ float g_delta[3][KK * LL];
__device__ float g_ST[DD * DD];         // ST[e*128+d] = S[d*128+e]

__global__ void routing_init_kernel(const float* __restrict__ Bin,
                                    const float* __restrict__ S)
{
    int idx = blockIdx.x * 256 + threadIdx.x;
    int d = idx >> 7;
    int e = idx & 127;
    g_ST[e * DD + d] = S[idx];
    if (blockIdx.x == 0) {
        for (int t = threadIdx.x; t < KK * LL; t += 256) {
            g_B[t] = Bin[t];
            g_delta[0][t] = 0.f;
            g_delta[1][t] = 0.f;
            g_delta[2][t] = 0.f;
        }
    }
}

__global__ void routing_update_kernel(int it)
{
    int t = threadIdx.x;
    if (t < KK * LL) g_B[t] += g_delta[it][t];
}

__global__ void __launch_bounds__(256, 3)
routing_iter_kernel(const float* __restrict__ cap,
                    const float* __restrict__ S,
                    const void*  __restrict__ seqp,
                    int it,
                    float* __restrict__ out)
{
    extern __shared__ float sm[];
    float*  cap4s_f = sm;
    float4* cap4s   = (float4*)sm;
    float*  W4      = sm + 13200;
    float*  red     = sm + 14000;
    float*  u4      = sm + 17072;
    float*  h4      = sm + 17584;
    float*  g4      = sm + 18096;
    (void)cap4s_f;

    const int b    = blockIdx.x;
    const int tid  = threadIdx.x;
    const int warp = tid >> 5;
    const int lane = tid & 31;

    // ---- sequence length (int32 vs int64 robust) --------------------------
    int n;
    {
        const int* si = (const int*)seqp;
        if (si[1] == 0) n = (int)(((const long long*)seqp)[b]);
        else            n = si[b];
    }

    // ---- masked softmax (warps 0-2) ---------------------------------------
    if (warp < 3) {
        const int k = warp;
        float v[7];
        float mx = -FLT_MAX;
        #pragma unroll
        for (int i = 0; i < 7; i++) {
            int l = lane + 32 * i;
            float x = -FLT_MAX;
            if (l < LL) x = (l < n) ? g_B[k * LL + l] : NEG_PAD;
            v[i] = x;
            mx = fmaxf(mx, x);
        }
        #pragma unroll
        for (int off = 16; off; off >>= 1)
            mx = fmaxf(mx, __shfl_xor_sync(0xffffffffu, mx, off));
        float s = 0.f;
        #pragma unroll
        for (int i = 0; i < 7; i++) {
            int l = lane + 32 * i;
            float e = (l < LL) ? expf(v[i] - mx) : 0.f;
            v[i] = e;
            s += e;
        }
        #pragma unroll
        for (int off = 16; off; off >>= 1)
            s += __shfl_xor_sync(0xffffffffu, s, off);
        float inv = 1.f / s;
        #pragma unroll
        for (int i = 0; i < 7; i++) {
            int l = lane + 32 * i;
            if (l < LL) {
                W4[l * 4 + k] = v[i] * inv;
                W4[l * 4 + 3] = 0.f;
            }
        }
    }
    __syncthreads();

    const float4* capb = (const float4*)(cap + (size_t)b * (LL * DD));
    const int j = lane;          // d-quad owned by this thread (d = 4j..4j+3)
    const int w = warp;

    // ---- fused sweep: load cap, accumulate u partials, stage l<100 --------
    // thread owns quad j; l = w + 8*itx (each l by exactly one warp)
    {
        float4 a0 = make_float4(0.f, 0.f, 0.f, 0.f);
        float4 a1 = a0, a2 = a0;
        #pragma unroll
        for (int bb = 0; bb < 5; bb++) {
            float4 c[5];
            #pragma unroll
            for (int s5 = 0; s5 < 5; s5++)           // batched loads: MLP=5
                c[s5] = capb[tid + 256 * (bb * 5 + s5)];
            #pragma unroll
            for (int s5 = 0; s5 < 5; s5++) {
                int itx = bb * 5 + s5;
                int l = w + 8 * itx;
                float4 wv = *(const float4*)(W4 + l * 4);   // broadcast
                a0.x = fmaf(wv.x, c[s5].x, a0.x); a0.y = fmaf(wv.x, c[s5].y, a0.y);
                a0.z = fmaf(wv.x, c[s5].z, a0.z); a0.w = fmaf(wv.x, c[s5].w, a0.w);
                a1.x = fmaf(wv.y, c[s5].x, a1.x); a1.y = fmaf(wv.y, c[s5].y, a1.y);
                a1.z = fmaf(wv.y, c[s5].z, a1.z); a1.w = fmaf(wv.y, c[s5].w, a1.w);
                a2.x = fmaf(wv.z, c[s5].x, a2.x); a2.y = fmaf(wv.z, c[s5].y, a2.y);
                a2.z = fmaf(wv.z, c[s5].z, a2.z); a2.w = fmaf(wv.z, c[s5].w, a2.w);
                if (l < LSTAGE)
                    cap4s[l * ROWQ + j] = c[s5];            // conflict-free STS.128
            }
        }
        float* rp = red + w * 384 + 4 * j;
        *(float4*)(rp)       = a0;
        *(float4*)(rp + 128) = a1;
        *(float4*)(rp + 256) = a2;
    }
    __syncthreads();
    for (int t = tid; t < 384; t += 256) {          // reduce 8 warps -> u4
        float s = 0.f;
        #pragma unroll
        for (int ww = 0; ww < 8; ww++) s += red[ww * 384 + t];
        u4[(t & 127) * 4 + (t >> 7)] = s;
    }
    __syncthreads();

    // ---- hraw[k,e] = sum_d u[k,d]*S[d,e] : warp covers all e, 16 d each ---
    {
        float4 a0 = make_float4(0.f, 0.f, 0.f, 0.f);
        float4 a1 = a0, a2 = a0;
        const int d0 = w * 16;
        #pragma unroll
        for (int dd = 0; dd < 16; dd++) {
            int d = d0 + dd;
            float4 sv = *(const float4*)(S + d * DD + 4 * j);   // coalesced
            float4 uv = *(const float4*)(u4 + d * 4);           // broadcast
            a0.x = fmaf(uv.x, sv.x, a0.x); a0.y = fmaf(uv.x, sv.y, a0.y);
            a0.z = fmaf(uv.x, sv.z, a0.z); a0.w = fmaf(uv.x, sv.w, a0.w);
            a1.x = fmaf(uv.y, sv.x, a1.x); a1.y = fmaf(uv.y, sv.y, a1.y);
            a1.z = fmaf(uv.y, sv.z, a1.z); a1.w = fmaf(uv.y, sv.w, a1.w);
            a2.x = fmaf(uv.z, sv.x, a2.x); a2.y = fmaf(uv.z, sv.y, a2.y);
            a2.z = fmaf(uv.z, sv.z, a2.z); a2.w = fmaf(uv.z, sv.w, a2.w);
        }
        float* rp = red + w * 384 + 4 * j;
        *(float4*)(rp)       = a0;
        *(float4*)(rp + 128) = a1;
        *(float4*)(rp + 256) = a2;
    }
    __syncthreads();
    for (int t = tid; t < 384; t += 256) {          // reduce -> h4 (raw)
        float s = 0.f;
        #pragma unroll
        for (int ww = 0; ww < 8; ww++) s += red[ww * 384 + t];
        h4[(t & 127) * 4 + (t >> 7)] = s;
    }
    __syncthreads();

    // ---- squash over k, write output --------------------------------------
    if (tid < 128) {
        const int e = tid;
        float h0 = h4[e * 4 + 0];
        float h1 = h4[e * 4 + 1];
        float h2 = h4[e * 4 + 2];
        float sq = h0 * h0 + h1 * h1 + h2 * h2;
        float scale = (sq / (1.f + sq)) * rsqrtf(sq + 1e-9f);
        h0 *= scale; h1 *= scale; h2 *= scale;
        float* op = out + (size_t)b * (KK * DD) + e;
        op[0]      = h0;
        op[DD]     = h1;
        op[2 * DD] = h2;
        h4[e * 4 + 0] = h0;
        h4[e * 4 + 1] = h1;
        h4[e * 4 + 2] = h2;
    }
    __syncthreads();

    // ---- g[k,d] = sum_e high[k,e]*ST[e,d] : warp covers all d, 16 e each --
    {
        float4 a0 = make_float4(0.f, 0.f, 0.f, 0.f);
        float4 a1 = a0, a2 = a0;
        const int e0 = w * 16;
        #pragma unroll
        for (int ee = 0; ee < 16; ee++) {
            int e = e0 + ee;
            float4 sv = *(const float4*)(g_ST + e * DD + 4 * j); // coalesced
            float4 hv = *(const float4*)(h4 + e * 4);            // broadcast
            a0.x = fmaf(hv.x, sv.x, a0.x); a0.y = fmaf(hv.x, sv.y, a0.y);
            a0.z = fmaf(hv.x, sv.z, a0.z); a0.w = fmaf(hv.x, sv.w, a0.w);
            a1.x = fmaf(hv.y, sv.x, a1.x); a1.y = fmaf(hv.y, sv.y, a1.y);
            a1.z = fmaf(hv.y, sv.z, a1.z); a1.w = fmaf(hv.y, sv.w, a1.w);
            a2.x = fmaf(hv.z, sv.x, a2.x); a2.y = fmaf(hv.z, sv.y, a2.y);
            a2.z = fmaf(hv.z, sv.z, a2.z); a2.w = fmaf(hv.z, sv.w, a2.w);
        }
        float* rp = red + w * 384 + 4 * j;
        *(float4*)(rp)       = a0;
        *(float4*)(rp + 128) = a1;
        *(float4*)(rp + 256) = a2;
    }
    __syncthreads();
    for (int t = tid; t < 384; t += 256) {          // reduce -> g4
        float s = 0.f;
        #pragma unroll
        for (int ww = 0; ww < 8; ww++) s += red[ww * 384 + t];
        g4[(t & 127) * 4 + (t >> 7)] = s;
    }
    __syncthreads();

    // ---- delta[k,l] += sum_d g[k,d]*cap[l,d] ------------------------------
    // Same (j, w) ownership as the sweep: per l, dot over this thread's quad,
    // then shfl-reduce over the 32 quads; smem half conflict-free, global L2-hot.
    {
        float G0[4], G1[4], G2[4];
        #pragma unroll
        for (int c = 0; c < 4; c++) {
            float4 gv = *(const float4*)(g4 + (4 * j + c) * 4);
            G0[c] = gv.x; G1[c] = gv.y; G2[c] = gv.z;
        }
        float* dp = g_delta[it];
        #pragma unroll 5
        for (int itx = 0; itx < 25; itx++) {
            int l = w + 8 * itx;
            float4 c4 = (l < LSTAGE) ? cap4s[l * ROWQ + j]      // LDS.128, cf
                                     : capb[l * 32 + j];        // LDG.128, L2-hot
            float a0 = fmaf(G0[0], c4.x, fmaf(G0[1], c4.y, fmaf(G0[2], c4.z, G0[3] * c4.w)));
            float a1 = fmaf(G1[0], c4.x, fmaf(G1[1], c4.y, fmaf(G1[2], c4.z, G1[3] * c4.w)));
            float a2 = fmaf(G2[0], c4.x, fmaf(G2[1], c4.y, fmaf(G2[2], c4.z, G2[3] * c4.w)));
            #pragma unroll
            for (int off = 16; off; off >>= 1) {
                a0 += __shfl_xor_sync(0xffffffffu, a0, off);
                a1 += __shfl_xor_sync(0xffffffffu, a1, off);
                a2 += __shfl_xor_sync(0xffffffffu, a2, off);
            }
            if (lane == 0) {
                atomicAdd(dp + l,          a0);
                atomicAdd(dp + LL + l,     a1);
                atomicAdd(dp + 2 * LL + l, a2);
            }
        }
    }
}

extern "C" void kernel_launch(void* const* d_in, const int* in_sizes, int n_in,
                              void* d_out, int out_size)
{
    (void)in_sizes; (void)n_in; (void)out_size;
    const float* cap  = (const float*)d_in[0];
    const float* Bin  = (const float*)d_in[1];
    const float* S    = (const float*)d_in[2];
    const void*  seqp = d_in[3];
    float* out = (float*)d_out;

    cudaFuncSetAttribute(routing_iter_kernel,
                         cudaFuncAttributeMaxDynamicSharedMemorySize, SMEM_BYTES);

    routing_init_kernel<<<64, 256>>>(Bin, S);

    routing_iter_kernel<<<NB, 256, SMEM_BYTES>>>(cap, S, seqp, 0, out);
    routing_update_kernel<<<1, 600>>>(0);
    routing_iter_kernel<<<NB, 256, SMEM_BYTES>>>(cap, S, seqp, 1, out);
    routing_update_kernel<<<1, 600>>>(1);
    routing_iter_kernel<<<NB, 256, SMEM_BYTES>>>(cap, S, seqp, 2, out);
}

// round 12
// speedup vs baseline: 1.6579x; 1.5946x over previous
#include <cuda_runtime.h>
#include <math.h>
#include <float.h>

#define NB 1024
#define LL 200
#define DD 128
#define KK 3
#define NEG_PAD (-65535.0f)

// Shared memory layout (floats), total 28136 = 112544 B (2 CTAs/SM, as R7):
//  cap_s [0,25800)      [200][129] staged tile
//  W4    [25800,26600)  [200][4]
//  u4    [26600,27112)  [128][4]
//  h4    [27112,27624)  [128][4]
//  g4    [27624,28136)  [128][4]
// Reduction scratch aliases dead regions (see per-pass comments).
#define SM_FLOATS 28136
#define SMEM_BYTES (SM_FLOATS * 4)

__device__ float g_B[KK * LL];
__device__ float g_delta[3][KK * LL];
__device__ float g_ST[DD * DD];         // ST[e*128+d] = S[d*128+e]

__global__ void routing_init_kernel(const float* __restrict__ Bin,
                                    const float* __restrict__ S)
{
    int idx = blockIdx.x * 256 + threadIdx.x;
    int d = idx >> 7;
    int e = idx & 127;
    g_ST[e * DD + d] = S[idx];
    if (blockIdx.x == 0) {
        for (int t = threadIdx.x; t < KK * LL; t += 256) {
            g_B[t] = Bin[t];
            g_delta[0][t] = 0.f;
            g_delta[1][t] = 0.f;
            g_delta[2][t] = 0.f;
        }
    }
}

__global__ void routing_update_kernel(int it)
{
    int t = threadIdx.x;
    if (t < KK * LL) g_B[t] += g_delta[it][t];
}

__global__ void __launch_bounds__(512, 2)
routing_iter_kernel(const float* __restrict__ cap,
                    const float* __restrict__ S,
                    const void*  __restrict__ seqp,
                    int it,
                    float* __restrict__ out)
{
    extern __shared__ float sm[];
    float* cap_s = sm;
    float* W4    = sm + 25800;
    float* u4    = sm + 26600;
    float* h4    = sm + 27112;
    float* g4    = sm + 27624;

    const int b    = blockIdx.x;
    const int tid  = threadIdx.x;
    const int warp = tid >> 5;
    const int lane = tid & 31;

    // ---- sequence length (int32 vs int64 robust) --------------------------
    int n;
    {
        const int* si = (const int*)seqp;
        if (si[1] == 0) n = (int)(((const long long*)seqp)[b]);
        else            n = si[b];
    }

    // ---- masked softmax (warps 0-2) — concurrent with staging below -------
    if (warp < 3) {
        const int k = warp;
        float v[7];
        float mx = -FLT_MAX;
        #pragma unroll
        for (int i = 0; i < 7; i++) {
            int l = lane + 32 * i;
            float x = -FLT_MAX;
            if (l < LL) x = (l < n) ? g_B[k * LL + l] : NEG_PAD;
            v[i] = x;
            mx = fmaxf(mx, x);
        }
        #pragma unroll
        for (int off = 16; off; off >>= 1)
            mx = fmaxf(mx, __shfl_xor_sync(0xffffffffu, mx, off));
        float s = 0.f;
        #pragma unroll
        for (int i = 0; i < 7; i++) {
            int l = lane + 32 * i;
            float e = (l < LL) ? expf(v[i] - mx) : 0.f;
            v[i] = e;
            s += e;
        }
        #pragma unroll
        for (int off = 16; off; off >>= 1)
            s += __shfl_xor_sync(0xffffffffu, s, off);
        float inv = 1.f / s;
        #pragma unroll
        for (int i = 0; i < 7; i++) {
            int l = lane + 32 * i;
            if (l < LL) {
                W4[l * 4 + k] = v[i] * inv;
                W4[l * 4 + 3] = 0.f;
            }
        }
    }

    // ---- stage low_capsule[b] into smem (pad 129) -------------------------
    {
        const float4* src = (const float4*)(cap + (size_t)b * (LL * DD));
        #pragma unroll
        for (int itx = 0; itx < 13; itx++) {
            int i = tid + itx * 512;                   // 0..6399 (+guard)
            if (i < 6400) {
                int l = i >> 5;
                int j = i & 31;
                float4 v = src[i];
                float* dst = cap_s + l * 129 + 4 * j;
                dst[0] = v.x; dst[1] = v.y; dst[2] = v.z; dst[3] = v.w;
            }
        }
    }
    __syncthreads();

    // ---- u[k,d] = sum_l W[k,l]*cap[l,d] : (e, l-quarter of 50) ------------
    // scratch = contiguous 1152 floats at u4 (spans u4+h4+g4[0:128), all dead)
    {
        const int e = tid & 127;
        const int q = tid >> 7;                         // 0..3
        float a0 = 0.f, a1 = 0.f, a2 = 0.f;
        const float*  cs = cap_s + (q * 50) * 129 + e;
        const float4* wp = (const float4*)W4 + q * 50;
        #pragma unroll 5
        for (int i = 0; i < 50; i++) {
            float4 wv = wp[i];                          // broadcast LDS.128
            float  c  = cs[i * 129];                    // conflict-free
            a0 = fmaf(wv.x, c, a0);
            a1 = fmaf(wv.y, c, a1);
            a2 = fmaf(wv.z, c, a2);
        }
        float* uscr = u4;
        if (q > 0) {
            uscr[(q - 1) * 384 +       e] = a0;
            uscr[(q - 1) * 384 + 128 + e] = a1;
            uscr[(q - 1) * 384 + 256 + e] = a2;
        }
        __syncthreads();
        float s0 = 0.f, s1 = 0.f, s2 = 0.f;
        if (tid < 128) {                                // q==0 holds own partials
            s0 = a0; s1 = a1; s2 = a2;
            #pragma unroll
            for (int qq = 0; qq < 3; qq++) {
                s0 += uscr[qq * 384 +       tid];
                s1 += uscr[qq * 384 + 128 + tid];
                s2 += uscr[qq * 384 + 256 + tid];
            }
        }
        __syncthreads();                                // reads done before overwrite
        if (tid < 128) {
            u4[tid * 4 + 0] = s0;
            u4[tid * 4 + 1] = s1;
            u4[tid * 4 + 2] = s2;
            u4[tid * 4 + 3] = 0.f;                      // pad for float4 reads
        }
    }
    __syncthreads();

    // ---- hraw[k,e] = sum_d u[k,d]*S[d,e] : (e, d-quarter of 32) -----------
    // scratch slots s<1024 -> h4+g4; s>=1024 -> W4 (dead after u-pass)
    {
        const int e = tid & 127;
        const int q = tid >> 7;
        float a0 = 0.f, a1 = 0.f, a2 = 0.f;
        const float* Sp = S + e;
        #pragma unroll 8
        for (int d = q * 32; d < q * 32 + 32; d++) {
            float4 uv = *(const float4*)(u4 + d * 4);  // broadcast
            float  s  = Sp[d * DD];                    // coalesced, L1-hot
            a0 = fmaf(uv.x, s, a0);
            a1 = fmaf(uv.y, s, a1);
            a2 = fmaf(uv.z, s, a2);
        }
        if (q > 0) {
            int base = (q - 1) * 384;
            int s0i = base + e, s1i = base + 128 + e, s2i = base + 256 + e;
            *((s0i < 1024) ? (h4 + s0i) : (W4 + s0i - 1024)) = a0;
            *((s1i < 1024) ? (h4 + s1i) : (W4 + s1i - 1024)) = a1;
            *((s2i < 1024) ? (h4 + s2i) : (W4 + s2i - 1024)) = a2;
        }
        __syncthreads();
        float s0 = 0.f, s1 = 0.f, s2 = 0.f;
        if (tid < 128) {
            s0 = a0; s1 = a1; s2 = a2;
            #pragma unroll
            for (int qq = 0; qq < 3; qq++) {
                int base = qq * 384;
                int i0 = base + tid, i1 = base + 128 + tid, i2 = base + 256 + tid;
                s0 += *((i0 < 1024) ? (h4 + i0) : (W4 + i0 - 1024));
                s1 += *((i1 < 1024) ? (h4 + i1) : (W4 + i1 - 1024));
                s2 += *((i2 < 1024) ? (h4 + i2) : (W4 + i2 - 1024));
            }
        }
        __syncthreads();
        if (tid < 128) {
            h4[tid * 4 + 0] = s0;
            h4[tid * 4 + 1] = s1;
            h4[tid * 4 + 2] = s2;
        }
    }
    __syncthreads();

    // ---- squash over k, write output, publish scaled high -----------------
    if (tid < 128) {
        const int e = tid;
        float h0 = h4[e * 4 + 0];
        float h1 = h4[e * 4 + 1];
        float h2 = h4[e * 4 + 2];
        float sq = h0 * h0 + h1 * h1 + h2 * h2;
        float scale = (sq / (1.f + sq)) * rsqrtf(sq + 1e-9f);
        h0 *= scale; h1 *= scale; h2 *= scale;
        float* op = out + (size_t)b * (KK * DD) + e;
        op[0]      = h0;
        op[DD]     = h1;
        op[2 * DD] = h2;
        h4[e * 4 + 0] = h0;
        h4[e * 4 + 1] = h1;
        h4[e * 4 + 2] = h2;
        h4[e * 4 + 3] = 0.f;                            // pad for float4 reads
    }
    __syncthreads();

    // ---- g[k,d] = sum_e high[k,e]*ST[e,d] : (d, e-quarter of 32) ----------
    // scratch slots s<512 -> u4 (dead); s>=512 -> W4 (dead)
    {
        const int d = tid & 127;
        const int q = tid >> 7;
        float a0 = 0.f, a1 = 0.f, a2 = 0.f;
        const float* STp = g_ST + d;
        #pragma unroll 8
        for (int e = q * 32; e < q * 32 + 32; e++) {
            float4 hv = *(const float4*)(h4 + e * 4);  // broadcast
            float  s  = STp[e * DD];                   // coalesced, L1-hot
            a0 = fmaf(hv.x, s, a0);
            a1 = fmaf(hv.y, s, a1);
            a2 = fmaf(hv.z, s, a2);
        }
        if (q > 0) {
            int base = (q - 1) * 384;
            int s0i = base + d, s1i = base + 128 + d, s2i = base + 256 + d;
            *((s0i < 512) ? (u4 + s0i) : (W4 + s0i - 512)) = a0;
            *((s1i < 512) ? (u4 + s1i) : (W4 + s1i - 512)) = a1;
            *((s2i < 512) ? (u4 + s2i) : (W4 + s2i - 512)) = a2;
        }
        __syncthreads();
        float s0 = 0.f, s1 = 0.f, s2 = 0.f;
        if (tid < 128) {
            s0 = a0; s1 = a1; s2 = a2;
            #pragma unroll
            for (int qq = 0; qq < 3; qq++) {
                int base = qq * 384;
                int i0 = base + tid, i1 = base + 128 + tid, i2 = base + 256 + tid;
                s0 += *((i0 < 512) ? (u4 + i0) : (W4 + i0 - 512));
                s1 += *((i1 < 512) ? (u4 + i1) : (W4 + i1 - 512));
                s2 += *((i2 < 512) ? (u4 + i2) : (W4 + i2 - 512));
            }
        }
        __syncthreads();
        if (tid < 128) {
            g4[tid * 4 + 0] = s0;
            g4[tid * 4 + 1] = s1;
            g4[tid * 4 + 2] = s2;
            g4[tid * 4 + 3] = 0.f;                      // pad for float4 reads
        }
    }
    __syncthreads();

    // ---- delta[k,l] += sum_d g[k,d]*cap[l,d] : 2 threads per row ----------
    // Bank stagger (+16 on half 1) keeps even/odd lanes conflict-free.
    {
        const int active = (tid < 400);
        const int l      = active ? (tid >> 1) : 0;     // rows 0..199
        const int half   = tid & 1;
        float a0 = 0.f, a1 = 0.f, a2 = 0.f;
        const float* cs = cap_s + l * 129;
        #pragma unroll 8
        for (int i = 0; i < 64; i++) {
            int d = half ? (64 + ((i + 16) & 63)) : i;
            float  c  = cs[d];                          // conflict-free
            float4 gv = *(const float4*)(g4 + d * 4);   // 2-addr broadcast
            a0 = fmaf(gv.x, c, a0);
            a1 = fmaf(gv.y, c, a1);
            a2 = fmaf(gv.z, c, a2);
        }
        a0 += __shfl_down_sync(0xffffffffu, a0, 1);     // combine d-halves
        a1 += __shfl_down_sync(0xffffffffu, a1, 1);
        a2 += __shfl_down_sync(0xffffffffu, a2, 1);
        if (active && half == 0) {
            float* dp = g_delta[it];
            atomicAdd(dp + l,          a0);
            atomicAdd(dp + LL + l,     a1);
            atomicAdd(dp + 2 * LL + l, a2);
        }
    }
}

extern "C" void kernel_launch(void* const* d_in, const int* in_sizes, int n_in,
                              void* d_out, int out_size)
{
    (void)in_sizes; (void)n_in; (void)out_size;
    const float* cap  = (const float*)d_in[0];
    const float* Bin  = (const float*)d_in[1];
    const float* S    = (const float*)d_in[2];
    const void*  seqp = d_in[3];
    float* out = (float*)d_out;

    cudaFuncSetAttribute(routing_iter_kernel,
                         cudaFuncAttributeMaxDynamicSharedMemorySize, SMEM_BYTES);

    routing_init_kernel<<<64, 256>>>(Bin, S);

    routing_iter_kernel<<<NB, 512, SMEM_BYTES>>>(cap, S, seqp, 0, out);
    routing_update_kernel<<<1, 600>>>(0);
    routing_iter_kernel<<<NB, 512, SMEM_BYTES>>>(cap, S, seqp, 1, out);
    routing_update_kernel<<<1, 600>>>(1);
    routing_iter_kernel<<<NB, 512, SMEM_BYTES>>>(cap, S, seqp, 2, out);
}